// round 4
// baseline (speedup 1.0000x reference)
#include <cuda_runtime.h>
#include <cuda_fp16.h>

#define NN 100000
#define NE 1600000
#define NF 256
#define NH 128
#define NC 8

// Scratch (static __device__ — no runtime allocation allowed)
__device__ __align__(16) __half2 d_gh[NN * 4];   // g = X @ Wc, fp16, 1.6 MB L2-resident
__device__ int   d_deg[NN];                      // zero at load; re-zeroed by k_xw each call
__device__ float d_dinv[NN];
__device__ __align__(16) float d_Wc[NF * NC];    // W1 @ Wfc
__device__ __align__(16) float d_bc[NC];         // b1 @ Wfc + bfc

// Detect whether edge_index is int64 (every odd 32-bit word == 0) or int32.
__device__ __forceinline__ bool ei_is64(const int* __restrict__ ei32) {
    return (__ldg(ei32 + 1) == 0) && (__ldg(ei32 + 3) == 0);
}

// ------- fused prologue: degree histogram (4 edges/thread) + weight fold -------
__global__ void k_degpre(const int* __restrict__ ei32,
                         const float* __restrict__ W1, const float* __restrict__ b1,
                         const float* __restrict__ Wfc, const float* __restrict__ bfc) {
    int t = blockIdx.x * blockDim.x + threadIdx.x;
    if (4 * t < NE) {
        bool is64 = ei_is64(ei32);
        int d0, d1, d2, d3;
        if (is64) {
            const int4* p = (const int4*)(ei32 + 2 * (size_t)NE);
            int4 a = p[t * 2], b = p[t * 2 + 1];
            d0 = a.x; d1 = a.z; d2 = b.x; d3 = b.z;
        } else {
            int4 a = ((const int4*)(ei32 + NE))[t];
            d0 = a.x; d1 = a.y; d2 = a.z; d3 = a.w;
        }
        atomicAdd(&d_deg[d0], 1);
        atomicAdd(&d_deg[d1], 1);
        atomicAdd(&d_deg[d2], 1);
        atomicAdd(&d_deg[d3], 1);
    }
    if (t < NF * NC) {
        int k = t >> 3, c = t & 7;
        float s = 0.f;
        #pragma unroll 8
        for (int j = 0; j < NH; j++) s = fmaf(W1[k * NH + j], Wfc[j * NC + c], s);
        d_Wc[t] = s;
    }
    if (t < NC) {
        float s = bfc[t];
        for (int j = 0; j < NH; j++) s = fmaf(b1[j], Wfc[j * NC + t], s);
        d_bc[t] = s;
    }
}

// ------- g = X @ Wc (warp per 2 rows) + out init + dinv + deg re-zero -------
__global__ void k_xw(const float* __restrict__ x, float* __restrict__ out) {
    int lane = threadIdx.x & 31;
    int warp_global = (blockIdx.x * blockDim.x + threadIdx.x) >> 5;
    int nwarps = (gridDim.x * blockDim.x) >> 5;

    // Lane owns features lane*8 .. lane*8+7; its 8x8 slab of Wc in registers.
    float w[8][NC];
    #pragma unroll
    for (int t = 0; t < 8; t++) {
        float4 w0 = ((const float4*)d_Wc)[(lane * 8 + t) * 2];
        float4 w1 = ((const float4*)d_Wc)[(lane * 8 + t) * 2 + 1];
        w[t][0] = w0.x; w[t][1] = w0.y; w[t][2] = w0.z; w[t][3] = w0.w;
        w[t][4] = w1.x; w[t][5] = w1.y; w[t][6] = w1.z; w[t][7] = w1.w;
    }
    bool b16 = lane & 16, b8 = lane & 8, b4 = lane & 4;
    int cidx = (lane >> 2) & 7;          // output column this lane finalizes
    float bcv = d_bc[cidx];

    for (int base = warp_global * 2; base < NN; base += nwarps * 2) {
        float4 a[2], b[2];
        int nr = (base + 1 < NN) ? 2 : 1;
        #pragma unroll
        for (int r = 0; r < 2; r++) {
            int row = (r < nr) ? base + r : base;
            const float4* xr = (const float4*)(x + (size_t)row * NF);
            a[r] = __ldg(xr + lane * 2);
            b[r] = __ldg(xr + lane * 2 + 1);
        }

        float v[2];
        #pragma unroll
        for (int r = 0; r < 2; r++) {
            float xs[8] = {a[r].x, a[r].y, a[r].z, a[r].w,
                           b[r].x, b[r].y, b[r].z, b[r].w};
            float acc[NC];
            #pragma unroll
            for (int c = 0; c < NC; c++) acc[c] = 0.f;
            #pragma unroll
            for (int t = 0; t < 8; t++)
                #pragma unroll
                for (int c = 0; c < NC; c++) acc[c] = fmaf(xs[t], w[t][c], acc[c]);

            // Value-splitting butterfly: 8 -> 4 -> 2 -> 1, then 2 scalar stages.
            float t4[4];
            #pragma unroll
            for (int j = 0; j < 4; j++) {
                float send = b16 ? acc[j] : acc[j + 4];
                float recv = __shfl_xor_sync(0xffffffffu, send, 16);
                t4[j] = (b16 ? acc[j + 4] : acc[j]) + recv;
            }
            float t2[2];
            #pragma unroll
            for (int j = 0; j < 2; j++) {
                float send = b8 ? t4[j] : t4[j + 2];
                float recv = __shfl_xor_sync(0xffffffffu, send, 8);
                t2[j] = (b8 ? t4[j + 2] : t4[j]) + recv;
            }
            float send = b4 ? t2[0] : t2[1];
            float recv = __shfl_xor_sync(0xffffffffu, send, 4);
            float vv = (b4 ? t2[1] : t2[0]) + recv;
            vv += __shfl_xor_sync(0xffffffffu, vv, 2);
            vv += __shfl_xor_sync(0xffffffffu, vv, 1);
            v[r] = vv;
        }

        #pragma unroll
        for (int r = 0; r < 2; r++) {
            if (r >= nr) break;
            int row = base + r;
            // lane 4*c holds column c for this row
            float vn = __shfl_down_sync(0xffffffffu, v[r], 4);   // next column's value
            int deg = d_deg[row] + 1;                            // +1 self-loop
            float dv = rsqrtf((float)deg);
            if ((lane & 3) == 0) {
                out[row * NC + cidx] = bcv + dv * dv * v[r];
                if ((lane & 7) == 0)   // c even: pack (c, c+1) into half2
                    d_gh[row * 4 + (cidx >> 1)] = __floats2half2_rn(v[r], vn);
            }
            if (lane == 0) {
                d_dinv[row] = dv;
                d_deg[row] = 0;        // reset for next graph replay
            }
        }
    }
}

// ---------------- edge aggregation: 2 edges / thread, fp16 gather, v4 RED ----------------
__global__ void k_edges(const int* __restrict__ ei32, float* __restrict__ out) {
    int t = blockIdx.x * blockDim.x + threadIdx.x;     // handles edges 2t, 2t+1
    if (2 * t >= NE) return;
    bool is64 = ei_is64(ei32);
    int s0, s1, d0, d1;
    if (is64) {
        int4 a = ((const int4*)ei32)[t];
        int4 b = ((const int4*)(ei32 + 2 * (size_t)NE))[t];
        s0 = a.x; s1 = a.z; d0 = b.x; d1 = b.z;
    } else {
        int2 a = ((const int2*)ei32)[t];
        int2 b = ((const int2*)(ei32 + NE))[t];
        s0 = a.x; s1 = a.y; d0 = b.x; d1 = b.y;
    }
    float n0 = __ldg(d_dinv + s0) * __ldg(d_dinv + d0);
    float n1 = __ldg(d_dinv + s1) * __ldg(d_dinv + d1);

    const uint4* gp = (const uint4*)d_gh;
    uint4 ga = __ldg(gp + s0);
    uint4 gb = __ldg(gp + s1);

    float2 a0 = __half22float2(*(const __half2*)&ga.x);
    float2 a1 = __half22float2(*(const __half2*)&ga.y);
    float2 a2 = __half22float2(*(const __half2*)&ga.z);
    float2 a3 = __half22float2(*(const __half2*)&ga.w);
    float2 c0 = __half22float2(*(const __half2*)&gb.x);
    float2 c1 = __half22float2(*(const __half2*)&gb.y);
    float2 c2 = __half22float2(*(const __half2*)&gb.z);
    float2 c3 = __half22float2(*(const __half2*)&gb.w);

    float4* oa = ((float4*)out) + d0 * 2;
    float4* ob = ((float4*)out) + d1 * 2;
    asm volatile("red.global.add.v4.f32 [%0], {%1, %2, %3, %4};"
                 :: "l"(oa), "f"(a0.x * n0), "f"(a0.y * n0), "f"(a1.x * n0), "f"(a1.y * n0) : "memory");
    asm volatile("red.global.add.v4.f32 [%0], {%1, %2, %3, %4};"
                 :: "l"(oa + 1), "f"(a2.x * n0), "f"(a2.y * n0), "f"(a3.x * n0), "f"(a3.y * n0) : "memory");
    asm volatile("red.global.add.v4.f32 [%0], {%1, %2, %3, %4};"
                 :: "l"(ob), "f"(c0.x * n1), "f"(c0.y * n1), "f"(c1.x * n1), "f"(c1.y * n1) : "memory");
    asm volatile("red.global.add.v4.f32 [%0], {%1, %2, %3, %4};"
                 :: "l"(ob + 1), "f"(c2.x * n1), "f"(c2.y * n1), "f"(c3.x * n1), "f"(c3.y * n1) : "memory");
}

extern "C" void kernel_launch(void* const* d_in, const int* in_sizes, int n_in,
                              void* d_out, int out_size) {
    const float* x    = (const float*)d_in[0];
    const int*   ei32 = (const int*)d_in[1];   // [2, NE], int32 or int64 (auto-detected)
    const float* W1   = (const float*)d_in[2];
    const float* b1   = (const float*)d_in[3];
    const float* Wfc  = (const float*)d_in[4];
    const float* bfc  = (const float*)d_in[5];
    float* out        = (float*)d_out;

    k_degpre<<<(NE / 4 + 255) / 256, 256>>>(ei32, W1, b1, Wfc, bfc);
    k_xw<<<1184, 256>>>(x, out);
    k_edges<<<(NE / 2 + 255) / 256, 256>>>(ei32, out);
}

// round 5
// speedup vs baseline: 1.3586x; 1.3586x over previous
#include <cuda_runtime.h>
#include <cuda_fp16.h>

#define NN 100000
#define NE 1600000
#define NF 256
#define NH 128
#define NC 8

// Scratch (static __device__ — no runtime allocation allowed)
__device__ __align__(16) __half d_gh[NN * NC];   // g = X @ Wc, fp16, 1.6 MB L2-resident
__device__ int   d_deg[NN];                      // zero at load; re-zeroed by k_xw each call
__device__ float d_dinv[NN];
__device__ __align__(16) float d_Wc[NF * NC];    // W1 @ Wfc
__device__ __align__(16) float d_bc[NC];         // b1 @ Wfc + bfc

// Detect whether edge_index is int64 (every odd 32-bit word == 0) or int32.
__device__ __forceinline__ bool ei_is64(const int* __restrict__ ei32) {
    return (__ldg(ei32 + 1) == 0) && (__ldg(ei32 + 3) == 0);
}

// ------- fused prologue: degree histogram (8 edges/thread) + weight fold -------
__global__ void k_degpre(const int* __restrict__ ei32,
                         const float* __restrict__ W1, const float* __restrict__ b1,
                         const float* __restrict__ Wfc, const float* __restrict__ bfc) {
    int t = blockIdx.x * blockDim.x + threadIdx.x;
    if (8 * t < NE) {
        bool is64 = ei_is64(ei32);
        int d[8];
        if (is64) {
            const int4* p = (const int4*)(ei32 + 2 * (size_t)NE);  // dst row (int64)
            int4 a = p[4 * t], b = p[4 * t + 1], c = p[4 * t + 2], e = p[4 * t + 3];
            d[0] = a.x; d[1] = a.z; d[2] = b.x; d[3] = b.z;
            d[4] = c.x; d[5] = c.z; d[6] = e.x; d[7] = e.z;
        } else {
            const int4* p = (const int4*)(ei32 + NE);
            int4 a = p[2 * t], b = p[2 * t + 1];
            d[0] = a.x; d[1] = a.y; d[2] = a.z; d[3] = a.w;
            d[4] = b.x; d[5] = b.y; d[6] = b.z; d[7] = b.w;
        }
        #pragma unroll
        for (int i = 0; i < 8; i++) atomicAdd(&d_deg[d[i]], 1);
    }
    if (t < NF * NC) {
        int k = t >> 3, c = t & 7;
        float s = 0.f;
        #pragma unroll 8
        for (int j = 0; j < NH; j++) s = fmaf(W1[k * NH + j], Wfc[j * NC + c], s);
        d_Wc[t] = s;
    }
    if (t < NC) {
        float s = bfc[t];
        for (int j = 0; j < NH; j++) s = fmaf(b1[j], Wfc[j * NC + t], s);
        d_bc[t] = s;
    }
}

// ------- g = X @ Wc : block-tiled through smem, thread = one output element -------
// 32 rows/block, 256 threads: thread (r = t>>3, c = t&7). No cross-lane comms.
#define TR 32
#define XS_STRIDE 264   // 1056 B row stride: rows hit bank offsets 0/32/64/96 -> conflict-free
__global__ void __launch_bounds__(256) k_xw(const float* __restrict__ x,
                                            float* __restrict__ out) {
    __shared__ float sx[TR * XS_STRIDE];   // 33 KB
    __shared__ float sw[NF * NC];          // 8 KB
    __shared__ float sbc[NC];

    int t = threadIdx.x;
    int base = blockIdx.x * TR;

    // Stage Wc + bias
    #pragma unroll
    for (int i = 0; i < 2; i++)
        ((float4*)sw)[t + i * 256] = ((const float4*)d_Wc)[t + i * 256];
    if (t < NC) sbc[t] = d_bc[t];

    // Stage X tile: 32 rows x 256 floats, fully coalesced float4 streams.
    {
        const float4* xg = (const float4*)(x + (size_t)base * NF);
        #pragma unroll
        for (int i = 0; i < 8; i++) {
            int idx = t + i * 256;               // float4 index within tile (2048 total)
            int row = idx >> 6, col4 = idx & 63;
            float4 v = __ldg(xg + idx);
            *(float4*)(sx + row * XS_STRIDE + col4 * 4) = v;
        }
    }
    __syncthreads();

    int r = t >> 3, c = t & 7;
    int row = base + r;

    const float4* xr = (const float4*)(sx + r * XS_STRIDE);
    float acc = 0.f;
    #pragma unroll 16
    for (int k4 = 0; k4 < 64; k4++) {
        float4 xv = xr[k4];
        acc = fmaf(xv.x, sw[(k4 * 4 + 0) * NC + c], acc);
        acc = fmaf(xv.y, sw[(k4 * 4 + 1) * NC + c], acc);
        acc = fmaf(xv.z, sw[(k4 * 4 + 2) * NC + c], acc);
        acc = fmaf(xv.w, sw[(k4 * 4 + 3) * NC + c], acc);
    }

    // Epilogue: out init (bias + self-loop), fp16 g, dinv, deg reset.
    int deg = d_deg[row] + 1;                 // +1 self-loop (all 8 lanes: L1 broadcast)
    float dv = rsqrtf((float)deg);
    out[row * NC + c] = sbc[c] + dv * dv * acc;
    d_gh[row * NC + c] = __float2half_rn(acc);
    if (c == 0) {                             // predicated after the reads above: safe in-warp
        d_dinv[row] = dv;
        d_deg[row] = 0;                       // reset for next graph replay
    }
}

// ---------------- edge aggregation: 2 edges / thread, fp16 gather, v4 RED ----------------
__global__ void k_edges(const int* __restrict__ ei32, float* __restrict__ out) {
    int t = blockIdx.x * blockDim.x + threadIdx.x;     // handles edges 2t, 2t+1
    if (2 * t >= NE) return;
    bool is64 = ei_is64(ei32);
    int s0, s1, d0, d1;
    if (is64) {
        int4 a = ((const int4*)ei32)[t];
        int4 b = ((const int4*)(ei32 + 2 * (size_t)NE))[t];
        s0 = a.x; s1 = a.z; d0 = b.x; d1 = b.z;
    } else {
        int2 a = ((const int2*)ei32)[t];
        int2 b = ((const int2*)(ei32 + NE))[t];
        s0 = a.x; s1 = a.y; d0 = b.x; d1 = b.y;
    }
    float n0 = __ldg(d_dinv + s0) * __ldg(d_dinv + d0);
    float n1 = __ldg(d_dinv + s1) * __ldg(d_dinv + d1);

    const uint4* gp = (const uint4*)d_gh;
    uint4 ga = __ldg(gp + s0);
    uint4 gb = __ldg(gp + s1);

    float2 a0 = __half22float2(*(const __half2*)&ga.x);
    float2 a1 = __half22float2(*(const __half2*)&ga.y);
    float2 a2 = __half22float2(*(const __half2*)&ga.z);
    float2 a3 = __half22float2(*(const __half2*)&ga.w);
    float2 c0 = __half22float2(*(const __half2*)&gb.x);
    float2 c1 = __half22float2(*(const __half2*)&gb.y);
    float2 c2 = __half22float2(*(const __half2*)&gb.z);
    float2 c3 = __half22float2(*(const __half2*)&gb.w);

    float4* oa = ((float4*)out) + d0 * 2;
    float4* ob = ((float4*)out) + d1 * 2;
    asm volatile("red.global.add.v4.f32 [%0], {%1, %2, %3, %4};"
                 :: "l"(oa), "f"(a0.x * n0), "f"(a0.y * n0), "f"(a1.x * n0), "f"(a1.y * n0) : "memory");
    asm volatile("red.global.add.v4.f32 [%0], {%1, %2, %3, %4};"
                 :: "l"(oa + 1), "f"(a2.x * n0), "f"(a2.y * n0), "f"(a3.x * n0), "f"(a3.y * n0) : "memory");
    asm volatile("red.global.add.v4.f32 [%0], {%1, %2, %3, %4};"
                 :: "l"(ob), "f"(c0.x * n1), "f"(c0.y * n1), "f"(c1.x * n1), "f"(c1.y * n1) : "memory");
    asm volatile("red.global.add.v4.f32 [%0], {%1, %2, %3, %4};"
                 :: "l"(ob + 1), "f"(c2.x * n1), "f"(c2.y * n1), "f"(c3.x * n1), "f"(c3.y * n1) : "memory");
}

extern "C" void kernel_launch(void* const* d_in, const int* in_sizes, int n_in,
                              void* d_out, int out_size) {
    const float* x    = (const float*)d_in[0];
    const int*   ei32 = (const int*)d_in[1];   // [2, NE], int32 or int64 (auto-detected)
    const float* W1   = (const float*)d_in[2];
    const float* b1   = (const float*)d_in[3];
    const float* Wfc  = (const float*)d_in[4];
    const float* bfc  = (const float*)d_in[5];
    float* out        = (float*)d_out;

    k_degpre<<<(NE / 8 + 255) / 256, 256>>>(ei32, W1, b1, Wfc, bfc);
    k_xw<<<NN / TR, 256>>>(x, out);
    k_edges<<<(NE / 2 + 255) / 256, 256>>>(ei32, out);
}

// round 6
// speedup vs baseline: 1.3898x; 1.0230x over previous
#include <cuda_runtime.h>
#include <cuda_fp16.h>

#define NN 100000
#define NE 1600000
#define NF 256
#define NH 128
#define NC 8

#define NB_XW 782          // xw blocks: 128 rows each (782*128 = 100096)
#define NB_DEG 1563        // deg blocks: 1024 edges each (1563*1024 >= 1.6M)

// Scratch (static __device__ — no runtime allocation allowed)
__device__ __align__(16) __half d_gh[NN * NC];   // g = X @ Wc, fp16, 1.6 MB L2-resident
__device__ int   d_deg[NN];                      // zero at load; re-zeroed by k_self each call
__device__ float d_dinv[NN];
__device__ __align__(16) float d_Wc[NF * NC];    // W1 @ Wfc
__device__ __align__(16) float d_bc[NC];         // b1 @ Wfc + bfc

// Detect whether edge_index is int64 (every odd 32-bit word == 0) or int32.
__device__ __forceinline__ bool ei_is64(const int* __restrict__ ei32) {
    return (__ldg(ei32 + 1) == 0) && (__ldg(ei32 + 3) == 0);
}

// ---------------- prologue: fold the two linear layers ----------------
__global__ void k_fold(const float* __restrict__ W1, const float* __restrict__ b1,
                       const float* __restrict__ Wfc, const float* __restrict__ bfc) {
    int t = blockIdx.x * blockDim.x + threadIdx.x;
    if (t < NF * NC) {
        int k = t >> 3, c = t & 7;
        float s = 0.f;
        #pragma unroll 8
        for (int j = 0; j < NH; j++) s = fmaf(__ldg(W1 + k * NH + j), __ldg(Wfc + j * NC + c), s);
        d_Wc[t] = s;
    }
    if (t < NC) {
        float s = bfc[t];
        for (int j = 0; j < NH; j++) s = fmaf(b1[j], Wfc[j * NC + t], s);
        d_bc[t] = s;
    }
}

// ------- fat middle kernel: xw blocks + deg blocks run CONCURRENTLY -------
// blockIdx < NB_XW  : g = X @ Wc for 128 rows (thread = (row, 4-col group))
// blockIdx >= NB_XW : degree histogram, 4 edges/thread
__global__ void __launch_bounds__(256) k_mid(const float* __restrict__ x,
                                             const int* __restrict__ ei32) {
    __shared__ float sw[NF * NC];      // 8 KB, used by xw branch only
    int t = threadIdx.x;

    if (blockIdx.x < NB_XW) {
        // ---- xw branch ----
        #pragma unroll
        for (int i = 0; i < 2; i++)
            ((float4*)sw)[t + i * 256] = ((const float4*)d_Wc)[t + i * 256];
        __syncthreads();

        int row = blockIdx.x * 128 + (t >> 1);
        if (row >= NN) return;
        int half = t & 1;                       // columns 4*half .. 4*half+3

        const float4* xr = (const float4*)(x + (size_t)row * NF);
        const float4* wp = (const float4*)(sw + half * 4);   // stride 2 float4s per k
        float4 acc = make_float4(0.f, 0.f, 0.f, 0.f);
        #pragma unroll 8
        for (int k4 = 0; k4 < 64; k4++) {
            float4 xv = __ldg(xr + k4);
            float4 w0 = wp[(k4 * 4 + 0) * 2];
            float4 w1 = wp[(k4 * 4 + 1) * 2];
            float4 w2 = wp[(k4 * 4 + 2) * 2];
            float4 w3 = wp[(k4 * 4 + 3) * 2];
            acc.x = fmaf(xv.x, w0.x, acc.x); acc.y = fmaf(xv.x, w0.y, acc.y);
            acc.z = fmaf(xv.x, w0.z, acc.z); acc.w = fmaf(xv.x, w0.w, acc.w);
            acc.x = fmaf(xv.y, w1.x, acc.x); acc.y = fmaf(xv.y, w1.y, acc.y);
            acc.z = fmaf(xv.y, w1.z, acc.z); acc.w = fmaf(xv.y, w1.w, acc.w);
            acc.x = fmaf(xv.z, w2.x, acc.x); acc.y = fmaf(xv.z, w2.y, acc.y);
            acc.z = fmaf(xv.z, w2.z, acc.z); acc.w = fmaf(xv.z, w2.w, acc.w);
            acc.x = fmaf(xv.w, w3.x, acc.x); acc.y = fmaf(xv.w, w3.y, acc.y);
            acc.z = fmaf(xv.w, w3.z, acc.z); acc.w = fmaf(xv.w, w3.w, acc.w);
        }
        __half2 h0 = __floats2half2_rn(acc.x, acc.y);
        __half2 h1 = __floats2half2_rn(acc.z, acc.w);
        uint2 pk = make_uint2(*(unsigned*)&h0, *(unsigned*)&h1);
        ((uint2*)d_gh)[row * 2 + half] = pk;
    } else {
        // ---- degree branch: 4 edges/thread ----
        int e4 = (blockIdx.x - NB_XW) * blockDim.x + t;    // handles edges 4*e4..+3
        if (4 * e4 >= NE) return;
        bool is64 = ei_is64(ei32);
        int d0, d1, d2, d3;
        if (is64) {
            const int4* p = (const int4*)(ei32 + 2 * (size_t)NE);
            int4 a = p[e4 * 2], b = p[e4 * 2 + 1];
            d0 = a.x; d1 = a.z; d2 = b.x; d3 = b.z;
        } else {
            int4 a = ((const int4*)(ei32 + NE))[e4];
            d0 = a.x; d1 = a.y; d2 = a.z; d3 = a.w;
        }
        atomicAdd(&d_deg[d0], 1);
        atomicAdd(&d_deg[d1], 1);
        atomicAdd(&d_deg[d2], 1);
        atomicAdd(&d_deg[d3], 1);
    }
}

// ------- self-loop + bias init of out; dinv; deg reset -------
__global__ void k_self(float* __restrict__ out) {
    int row = blockIdx.x * blockDim.x + threadIdx.x;
    if (row >= NN) return;
    int deg = d_deg[row] + 1;                 // +1 self-loop
    float dv = rsqrtf((float)deg);
    float wgt = dv * dv;
    uint4 g = ((const uint4*)d_gh)[row];
    float2 g0 = __half22float2(*(const __half2*)&g.x);
    float2 g1 = __half22float2(*(const __half2*)&g.y);
    float2 g2 = __half22float2(*(const __half2*)&g.z);
    float2 g3 = __half22float2(*(const __half2*)&g.w);
    float4 b0 = ((const float4*)d_bc)[0];
    float4 b1 = ((const float4*)d_bc)[1];
    ((float4*)out)[row * 2] = make_float4(b0.x + wgt * g0.x, b0.y + wgt * g0.y,
                                          b0.z + wgt * g1.x, b0.w + wgt * g1.y);
    ((float4*)out)[row * 2 + 1] = make_float4(b1.x + wgt * g2.x, b1.y + wgt * g2.y,
                                              b1.z + wgt * g3.x, b1.w + wgt * g3.y);
    d_dinv[row] = dv;
    d_deg[row] = 0;                           // reset for next graph replay
}

// ---------------- edge aggregation: 2 edges / thread, fp16 gather, v4 RED ----------------
__global__ void k_edges(const int* __restrict__ ei32, float* __restrict__ out) {
    int t = blockIdx.x * blockDim.x + threadIdx.x;     // handles edges 2t, 2t+1
    if (2 * t >= NE) return;
    bool is64 = ei_is64(ei32);
    int s0, s1, d0, d1;
    if (is64) {
        int4 a = ((const int4*)ei32)[t];
        int4 b = ((const int4*)(ei32 + 2 * (size_t)NE))[t];
        s0 = a.x; s1 = a.z; d0 = b.x; d1 = b.z;
    } else {
        int2 a = ((const int2*)ei32)[t];
        int2 b = ((const int2*)(ei32 + NE))[t];
        s0 = a.x; s1 = a.y; d0 = b.x; d1 = b.y;
    }
    float n0 = __ldg(d_dinv + s0) * __ldg(d_dinv + d0);
    float n1 = __ldg(d_dinv + s1) * __ldg(d_dinv + d1);

    const uint4* gp = (const uint4*)d_gh;
    uint4 ga = __ldg(gp + s0);
    uint4 gb = __ldg(gp + s1);

    float2 a0 = __half22float2(*(const __half2*)&ga.x);
    float2 a1 = __half22float2(*(const __half2*)&ga.y);
    float2 a2 = __half22float2(*(const __half2*)&ga.z);
    float2 a3 = __half22float2(*(const __half2*)&ga.w);
    float2 c0 = __half22float2(*(const __half2*)&gb.x);
    float2 c1 = __half22float2(*(const __half2*)&gb.y);
    float2 c2 = __half22float2(*(const __half2*)&gb.z);
    float2 c3 = __half22float2(*(const __half2*)&gb.w);

    float4* oa = ((float4*)out) + d0 * 2;
    float4* ob = ((float4*)out) + d1 * 2;
    asm volatile("red.global.add.v4.f32 [%0], {%1, %2, %3, %4};"
                 :: "l"(oa), "f"(a0.x * n0), "f"(a0.y * n0), "f"(a1.x * n0), "f"(a1.y * n0) : "memory");
    asm volatile("red.global.add.v4.f32 [%0], {%1, %2, %3, %4};"
                 :: "l"(oa + 1), "f"(a2.x * n0), "f"(a2.y * n0), "f"(a3.x * n0), "f"(a3.y * n0) : "memory");
    asm volatile("red.global.add.v4.f32 [%0], {%1, %2, %3, %4};"
                 :: "l"(ob), "f"(c0.x * n1), "f"(c0.y * n1), "f"(c1.x * n1), "f"(c1.y * n1) : "memory");
    asm volatile("red.global.add.v4.f32 [%0], {%1, %2, %3, %4};"
                 :: "l"(ob + 1), "f"(c2.x * n1), "f"(c2.y * n1), "f"(c3.x * n1), "f"(c3.y * n1) : "memory");
}

extern "C" void kernel_launch(void* const* d_in, const int* in_sizes, int n_in,
                              void* d_out, int out_size) {
    const float* x    = (const float*)d_in[0];
    const int*   ei32 = (const int*)d_in[1];   // [2, NE], int32 or int64 (auto-detected)
    const float* W1   = (const float*)d_in[2];
    const float* b1   = (const float*)d_in[3];
    const float* Wfc  = (const float*)d_in[4];
    const float* bfc  = (const float*)d_in[5];
    float* out        = (float*)d_out;

    k_fold<<<8, 256>>>(W1, b1, Wfc, bfc);
    k_mid<<<NB_XW + NB_DEG, 256>>>(x, ei32);
    k_self<<<(NN + 255) / 256, 256>>>(out);
    k_edges<<<(NE / 2 + 255) / 256, 256>>>(ei32, out);
}

// round 7
// speedup vs baseline: 1.5814x; 1.1379x over previous
#include <cuda_runtime.h>
#include <cuda_fp16.h>

#define NN 100000
#define NE 1600000
#define NF 256
#define NH 128
#define NC 8

#define NB_FOLD 8
#define NB_DEG 1563       // 1024 edges each

// Scratch (static __device__ — no runtime allocation allowed)
__device__ __align__(16) __half d_gh[NN * NC];   // fp16(g * dinv_src), 1.6 MB L2-resident
__device__ __align__(16) float d_acc[NN * NC];   // raw edge sums; zero at load, re-zeroed by k_post
__device__ int   d_deg[NN];                      // zero at load; re-zeroed by k_xw
__device__ float d_dinv[NN];
__device__ __align__(16) float d_Wc[NF * NC];    // W1 @ Wfc
__device__ __align__(16) float d_bc[NC];         // b1 @ Wfc + bfc

// Detect whether edge_index is int64 (every odd 32-bit word == 0) or int32.
__device__ __forceinline__ bool ei_is64(const int* __restrict__ ei32) {
    return (__ldg(ei32 + 1) == 0) && (__ldg(ei32 + 3) == 0);
}

// ------- k1: weight fold (blocks 0..7) || degree histogram (rest) -------
__global__ void __launch_bounds__(256) k_pre(const int* __restrict__ ei32,
                                             const float* __restrict__ W1,
                                             const float* __restrict__ b1,
                                             const float* __restrict__ Wfc,
                                             const float* __restrict__ bfc) {
    int t = threadIdx.x;
    if (blockIdx.x < NB_FOLD) {
        int idx = blockIdx.x * 256 + t;
        if (idx < NF * NC) {
            int k = idx >> 3, c = idx & 7;
            float s = 0.f;
            #pragma unroll 8
            for (int j = 0; j < NH; j++)
                s = fmaf(__ldg(W1 + k * NH + j), __ldg(Wfc + j * NC + c), s);
            d_Wc[idx] = s;
        }
        if (idx < NC) {
            float s = bfc[idx];
            for (int j = 0; j < NH; j++) s = fmaf(b1[j], Wfc[j * NC + idx], s);
            d_bc[idx] = s;
        }
    } else {
        int e4 = (blockIdx.x - NB_FOLD) * 256 + t;     // handles edges 4*e4..+3
        if (4 * e4 >= NE) return;
        bool is64 = ei_is64(ei32);
        int d0, d1, d2, d3;
        if (is64) {
            const int4* p = (const int4*)(ei32 + 2 * (size_t)NE);
            int4 a = p[e4 * 2], b = p[e4 * 2 + 1];
            d0 = a.x; d1 = a.z; d2 = b.x; d3 = b.z;
        } else {
            int4 a = ((const int4*)(ei32 + NE))[e4];
            d0 = a.x; d1 = a.y; d2 = a.z; d3 = a.w;
        }
        atomicAdd(&d_deg[d0], 1);
        atomicAdd(&d_deg[d1], 1);
        atomicAdd(&d_deg[d2], 1);
        atomicAdd(&d_deg[d3], 1);
    }
}

// ------- k2: gh = fp16((X @ Wc) * dinv); dinv; deg reset -------
// 128 rows/block, 2 threads/row (4 columns each).
__global__ void __launch_bounds__(256) k_xw(const float* __restrict__ x) {
    __shared__ float sw[NF * NC];      // 8 KB
    int t = threadIdx.x;
    #pragma unroll
    for (int i = 0; i < 2; i++)
        ((float4*)sw)[t + i * 256] = ((const float4*)d_Wc)[t + i * 256];
    __syncthreads();

    int row = blockIdx.x * 128 + (t >> 1);
    if (row >= NN) return;
    int half = t & 1;                       // columns 4*half .. 4*half+3

    const float4* xr = (const float4*)(x + (size_t)row * NF);
    const float4* wp = (const float4*)(sw + half * 4);   // stride 2 float4s per k
    float4 acc = make_float4(0.f, 0.f, 0.f, 0.f);
    #pragma unroll 8
    for (int k4 = 0; k4 < 64; k4++) {
        float4 xv = __ldg(xr + k4);
        float4 w0 = wp[(k4 * 4 + 0) * 2];
        float4 w1 = wp[(k4 * 4 + 1) * 2];
        float4 w2 = wp[(k4 * 4 + 2) * 2];
        float4 w3 = wp[(k4 * 4 + 3) * 2];
        acc.x = fmaf(xv.x, w0.x, acc.x); acc.y = fmaf(xv.x, w0.y, acc.y);
        acc.z = fmaf(xv.x, w0.z, acc.z); acc.w = fmaf(xv.x, w0.w, acc.w);
        acc.x = fmaf(xv.y, w1.x, acc.x); acc.y = fmaf(xv.y, w1.y, acc.y);
        acc.z = fmaf(xv.y, w1.z, acc.z); acc.w = fmaf(xv.y, w1.w, acc.w);
        acc.x = fmaf(xv.z, w2.x, acc.x); acc.y = fmaf(xv.z, w2.y, acc.y);
        acc.z = fmaf(xv.z, w2.z, acc.z); acc.w = fmaf(xv.z, w2.w, acc.w);
        acc.x = fmaf(xv.w, w3.x, acc.x); acc.y = fmaf(xv.w, w3.y, acc.y);
        acc.z = fmaf(xv.w, w3.z, acc.z); acc.w = fmaf(xv.w, w3.w, acc.w);
    }

    int deg = d_deg[row] + 1;               // +1 self-loop (L1 broadcast for the pair)
    float dv = rsqrtf((float)deg);
    __half2 h0 = __floats2half2_rn(acc.x * dv, acc.y * dv);
    __half2 h1 = __floats2half2_rn(acc.z * dv, acc.w * dv);
    ((uint2*)d_gh)[row * 2 + half] = make_uint2(*(unsigned*)&h0, *(unsigned*)&h1);
    if (half == 0) {
        d_dinv[row] = dv;
        d_deg[row] = 0;                     // reset for next graph replay
    }
}

// ------- k3: edges -> raw sums. 2 edges/thread; gather gh_s, RED into acc_d -------
__global__ void k_edges(const int* __restrict__ ei32) {
    int t = blockIdx.x * blockDim.x + threadIdx.x;     // handles edges 2t, 2t+1
    if (2 * t >= NE) return;
    bool is64 = ei_is64(ei32);
    int s0, s1, d0, d1;
    if (is64) {
        int4 a = ((const int4*)ei32)[t];
        int4 b = ((const int4*)(ei32 + 2 * (size_t)NE))[t];
        s0 = a.x; s1 = a.z; d0 = b.x; d1 = b.z;
    } else {
        int2 a = ((const int2*)ei32)[t];
        int2 b = ((const int2*)(ei32 + NE))[t];
        s0 = a.x; s1 = a.y; d0 = b.x; d1 = b.y;
    }
    const uint4* gp = (const uint4*)d_gh;
    uint4 ga = __ldg(gp + s0);
    uint4 gb = __ldg(gp + s1);

    float2 a0 = __half22float2(*(const __half2*)&ga.x);
    float2 a1 = __half22float2(*(const __half2*)&ga.y);
    float2 a2 = __half22float2(*(const __half2*)&ga.z);
    float2 a3 = __half22float2(*(const __half2*)&ga.w);
    float2 c0 = __half22float2(*(const __half2*)&gb.x);
    float2 c1 = __half22float2(*(const __half2*)&gb.y);
    float2 c2 = __half22float2(*(const __half2*)&gb.z);
    float2 c3 = __half22float2(*(const __half2*)&gb.w);

    float4* oa = ((float4*)d_acc) + d0 * 2;
    float4* ob = ((float4*)d_acc) + d1 * 2;
    asm volatile("red.global.add.v4.f32 [%0], {%1, %2, %3, %4};"
                 :: "l"(oa), "f"(a0.x), "f"(a0.y), "f"(a1.x), "f"(a1.y) : "memory");
    asm volatile("red.global.add.v4.f32 [%0], {%1, %2, %3, %4};"
                 :: "l"(oa + 1), "f"(a2.x), "f"(a2.y), "f"(a3.x), "f"(a3.y) : "memory");
    asm volatile("red.global.add.v4.f32 [%0], {%1, %2, %3, %4};"
                 :: "l"(ob), "f"(c0.x), "f"(c0.y), "f"(c1.x), "f"(c1.y) : "memory");
    asm volatile("red.global.add.v4.f32 [%0], {%1, %2, %3, %4};"
                 :: "l"(ob + 1), "f"(c2.x), "f"(c2.y), "f"(c3.x), "f"(c3.y) : "memory");
}

// ------- k4: out = bc + dinv * (acc + gh);  acc reset for next replay -------
__global__ void k_post(float* __restrict__ out) {
    int row = blockIdx.x * blockDim.x + threadIdx.x;
    if (row >= NN) return;
    float dv = d_dinv[row];
    float4 s0 = ((const float4*)d_acc)[row * 2];
    float4 s1 = ((const float4*)d_acc)[row * 2 + 1];
    uint4 g = ((const uint4*)d_gh)[row];
    float2 g0 = __half22float2(*(const __half2*)&g.x);
    float2 g1 = __half22float2(*(const __half2*)&g.y);
    float2 g2 = __half22float2(*(const __half2*)&g.z);
    float2 g3 = __half22float2(*(const __half2*)&g.w);
    float4 b0 = ((const float4*)d_bc)[0];
    float4 b1 = ((const float4*)d_bc)[1];
    ((float4*)out)[row * 2] = make_float4(
        fmaf(dv, s0.x + g0.x, b0.x), fmaf(dv, s0.y + g0.y, b0.y),
        fmaf(dv, s0.z + g1.x, b0.z), fmaf(dv, s0.w + g1.y, b0.w));
    ((float4*)out)[row * 2 + 1] = make_float4(
        fmaf(dv, s1.x + g2.x, b1.x), fmaf(dv, s1.y + g2.y, b1.y),
        fmaf(dv, s1.z + g3.x, b1.z), fmaf(dv, s1.w + g3.y, b1.w));
    float4 z = make_float4(0.f, 0.f, 0.f, 0.f);
    ((float4*)d_acc)[row * 2] = z;          // reset for next graph replay
    ((float4*)d_acc)[row * 2 + 1] = z;
}

extern "C" void kernel_launch(void* const* d_in, const int* in_sizes, int n_in,
                              void* d_out, int out_size) {
    const float* x    = (const float*)d_in[0];
    const int*   ei32 = (const int*)d_in[1];   // [2, NE], int32 or int64 (auto-detected)
    const float* W1   = (const float*)d_in[2];
    const float* b1   = (const float*)d_in[3];
    const float* Wfc  = (const float*)d_in[4];
    const float* bfc  = (const float*)d_in[5];
    float* out        = (float*)d_out;

    k_pre<<<NB_FOLD + NB_DEG, 256>>>(ei32, W1, b1, Wfc, bfc);
    k_xw<<<(NN + 127) / 128, 256>>>(x);
    k_edges<<<(NE / 2 + 255) / 256, 256>>>(ei32);
    k_post<<<(NN + 255) / 256, 256>>>(out);
}